// round 15
// baseline (speedup 1.0000x reference)
#include <cuda_runtime.h>
#include <cuda_fp16.h>
#include <math.h>
#include <stdint.h>

// Problem shapes
#define B_   8
#define HW_  32
#define T_   31
#define NF_  256
#define E_   512
#define M_   2048
#define H_   8
#define DH_  64

#define ROWS_Q   (B_ * NF_)            // 2048
#define ROWS_KV  (B_ * T_ * NF_)       // 63488

// hgemm tiling: CTA 128x128, K-chunk 64 (fp16), 3-stage, 4 warps of 64x64
#define TK 64
#define NSTAGE 3
#define STAGE_BYTES 32768
#define SMEM_TOTAL (NSTAGE * STAGE_BYTES)   // 98304

// Attention smem (bytes)
#define AQ_B 0
#define AP_B 32768
#define AK_B 65536
#define AV_B 81920
#define ATTN_SMEM 98304

// ---------------- static scratch ----------------
__device__ __half g_qln [ (size_t)ROWS_Q  * E_ ];
__device__ __half g_q   [ (size_t)ROWS_Q  * E_ ];
__device__ __half g_kvln[ (size_t)ROWS_KV * E_ ];
__device__ __half g_kv  [ (size_t)ROWS_KV * 1024 ];
__device__ __half g_t1h [ (size_t)ROWS_KV * E_ ];
__device__ __half g_t2h [ (size_t)ROWS_KV * E_ ];
__device__ __half g_hid [ (size_t)ROWS_KV * M_ ];
__device__ __half g_wtA [ (size_t)4 * E_ * E_ ];
__device__ __half g_wtB [ (size_t)4 * E_ * M_ ];
__device__ __half g_wqT [ (size_t)E_ * E_ ];
__device__ float  g_bkv [ 1024 ];

// ---------------- helpers ----------------
__device__ __forceinline__ float gelu_exact(float x) {
    return 0.5f * x * (1.0f + erff(x * 0.70710678118654752f));
}
__device__ __forceinline__ uint32_t smem_u32(const void* p) {
    uint32_t a;
    asm("{ .reg .u64 t; cvta.to.shared.u64 t, %1; cvt.u32.u64 %0, t; }" : "=r"(a) : "l"(p));
    return a;
}
__device__ __forceinline__ void cp16(uint32_t s, const void* g) {
    asm volatile("cp.async.cg.shared.global [%0], [%1], 16;" :: "r"(s), "l"(g));
}
__device__ __forceinline__ void ldsm4(uint32_t* r, uint32_t a) {
    asm volatile("ldmatrix.sync.aligned.m8n8.x4.shared.b16 {%0,%1,%2,%3}, [%4];"
        : "=r"(r[0]), "=r"(r[1]), "=r"(r[2]), "=r"(r[3]) : "r"(a));
}
__device__ __forceinline__ void ldsm4t(uint32_t* r, uint32_t a) {
    asm volatile("ldmatrix.sync.aligned.m8n8.x4.trans.shared.b16 {%0,%1,%2,%3}, [%4];"
        : "=r"(r[0]), "=r"(r[1]), "=r"(r[2]), "=r"(r[3]) : "r"(a));
}
__device__ __forceinline__ void mma_f16(float* d, const uint32_t* a, uint32_t b0, uint32_t b1) {
    asm volatile(
        "mma.sync.aligned.m16n8k16.row.col.f32.f16.f16.f32 "
        "{%0,%1,%2,%3}, {%4,%5,%6,%7}, {%8,%9}, {%0,%1,%2,%3};"
        : "+f"(d[0]), "+f"(d[1]), "+f"(d[2]), "+f"(d[3])
        : "r"(a[0]), "r"(a[1]), "r"(a[2]), "r"(a[3]), "r"(b0), "r"(b1));
}

__device__ __forceinline__ float blk_sum4(float v, float* sb) {   // 128 threads
    #pragma unroll
    for (int o = 16; o; o >>= 1) v += __shfl_xor_sync(0xffffffffu, v, o);
    if ((threadIdx.x & 31) == 0) sb[threadIdx.x >> 5] = v;
    __syncthreads();
    float r = sb[0] + sb[1] + sb[2] + sb[3];
    __syncthreads();
    return r;
}
__device__ __forceinline__ float blk_sum8(float v, float* sb) {   // 256 threads
    #pragma unroll
    for (int o = 16; o; o >>= 1) v += __shfl_xor_sync(0xffffffffu, v, o);
    if ((threadIdx.x & 31) == 0) sb[threadIdx.x >> 5] = v;
    __syncthreads();
    float r = sb[0] + sb[1] + sb[2] + sb[3] + sb[4] + sb[5] + sb[6] + sb[7];
    __syncthreads();
    return r;
}

// ---------------- fused pre-work: 8 weight transposes + bias concat + input LN ----------------
struct TSeg { const float* W; __half* WT; int K; int N; int blk0; };
struct PreDesc {
    TSeg s[8];
    const float *bk, *bv; float* bkvO;
    const float *X, *gq, *bq, *gkv, *bkvLN;
    __half *out_q, *out_kv;
};

__global__ void __launch_bounds__(256) pre_all(PreDesc d, int nblk_t)
{
    __shared__ float shm[32 * 33];
    int blk = blockIdx.x;

    if (blk < nblk_t) {                                  // --- transpose segment ---
        float (*t)[33] = (float(*)[33])shm;
        int si = 0;
        #pragma unroll
        for (int j = 1; j < 8; j++) if (blk >= d.s[j].blk0) si = j;
        const TSeg sg = d.s[si];
        int b = blk - sg.blk0;
        int nx = sg.N >> 5;
        int n0 = (b % nx) * 32, k0 = (b / nx) * 32;
        int tx = threadIdx.x & 31, ty = threadIdx.x >> 5;
        #pragma unroll
        for (int j = 0; j < 32; j += 8)
            t[ty + j][tx] = sg.W[(size_t)(k0 + ty + j) * sg.N + n0 + tx];
        __syncthreads();
        #pragma unroll
        for (int j = 0; j < 32; j += 8)
            sg.WT[(size_t)(n0 + ty + j) * sg.K + k0 + tx] = __float2half_rn(t[tx][ty + j]);
        return;
    }
    if (blk == nblk_t) {                                 // --- bias concat ---
        int i = threadIdx.x;
        #pragma unroll
        for (int j = 0; j < 4; j++) {
            int idx = i + j * 256;
            d.bkvO[idx] = (idx < 512) ? d.bk[idx] : d.bv[idx - 512];
        }
        return;
    }

    // --- input LN row ---
    int r = blk - nblk_t - 1;                            // 0 .. 8191
    int b = r >> 13;
    int t = (r >> 8) & 31;
    int n = r & 255;
    int c = threadIdx.x * 2;

    float2 xv = *(const float2*)(d.X + (size_t)r * E_ + c);
    float s = xv.x + xv.y;
    float mean = blk_sum8(s, shm) * (1.0f / E_);
    float d0 = xv.x - mean, d1 = xv.y - mean;
    float var = blk_sum8(d0 * d0 + d1 * d1, shm) * (1.0f / E_);
    float rs = rsqrtf(var + 1e-6f);

    const float *g, *be; __half* dst;
    if (t == 0) { g = d.gq;  be = d.bq;    dst = d.out_q  + ((size_t)(b * NF_ + n)) * E_; }
    else        { g = d.gkv; be = d.bkvLN; dst = d.out_kv + ((size_t)((b * T_ + (t - 1)) * NF_ + n)) * E_; }

    float2 gg = *(const float2*)(g + c);
    float2 bb = *(const float2*)(be + c);
    __half2 h = __floats2half2_rn(d0 * rs * gg.x + bb.x, d1 * rs * gg.y + bb.y);
    *(uint32_t*)(dst + c) = *(uint32_t*)&h;
}

// ---------------- fused double LayerNorm: fp16 in -> fp16 out ----------------
__global__ void __launch_bounds__(128) dual_ln_kernel(
    const __half* __restrict__ X,
    const float* __restrict__ g1, const float* __restrict__ b1,
    const float* __restrict__ g2, const float* __restrict__ b2,
    __half* __restrict__ Y)
{
    __shared__ float sb[4];
    size_t r = blockIdx.x;
    int c = threadIdx.x * 4;
    uint2 xu = *(const uint2*)(X + r * E_ + c);
    float2 xa = __half22float2(*(__half2*)&xu.x);
    float2 xb = __half22float2(*(__half2*)&xu.y);

    float s = xa.x + xa.y + xb.x + xb.y;
    float mean = blk_sum4(s, sb) * (1.0f / E_);
    float d0 = xa.x - mean, d1 = xa.y - mean, d2 = xb.x - mean, d3 = xb.y - mean;
    float var = blk_sum4(d0*d0 + d1*d1 + d2*d2 + d3*d3, sb) * (1.0f / E_);
    float rs = rsqrtf(var + 1e-6f);

    float4 gg = *(const float4*)(g1 + c);
    float4 bb = *(const float4*)(b1 + c);
    float y0 = d0 * rs * gg.x + bb.x;
    float y1 = d1 * rs * gg.y + bb.y;
    float y2 = d2 * rs * gg.z + bb.z;
    float y3 = d3 * rs * gg.w + bb.w;

    float s2 = y0 + y1 + y2 + y3;
    float mean2 = blk_sum4(s2, sb) * (1.0f / E_);
    float e0 = y0 - mean2, e1 = y1 - mean2, e2 = y2 - mean2, e3 = y3 - mean2;
    float var2 = blk_sum4(e0*e0 + e1*e1 + e2*e2 + e3*e3, sb) * (1.0f / E_);
    float rs2 = rsqrtf(var2 + 1e-6f);

    float4 gg2 = *(const float4*)(g2 + c);
    float4 bb2 = *(const float4*)(b2 + c);
    __half2 h0 = __floats2half2_rn(e0 * rs2 * gg2.x + bb2.x, e1 * rs2 * gg2.y + bb2.y);
    __half2 h1 = __floats2half2_rn(e2 * rs2 * gg2.z + bb2.z, e3 * rs2 * gg2.w + bb2.w);
    uint2 u; u.x = *(uint32_t*)&h0; u.y = *(uint32_t*)&h1;
    *(uint2*)(Y + r * E_ + c) = u;
}

// ---------------- fp16 mma GEMM body (R12 tiling + register-double-buffered fragments) ----------------
template<bool DO_GELU, bool DO_RES, typename OT>
__device__ __forceinline__ void hgemm_body(
    const __half* __restrict__ A, const __half* __restrict__ BT,
    const float* __restrict__ bias, const __half* __restrict__ res,
    OT* __restrict__ C, int N, int K, int brow, int bcol, char* dsm)
{
    const uint32_t sb0 = smem_u32(dsm);
    const int tid = threadIdx.x, warp = tid >> 5, lane = tid & 31;
    const int wm = (warp >> 1) * 64, wn = (warp & 1) * 64;

    const int rf = tid >> 3, gf = tid & 7;
    const uint32_t fso = (uint32_t)rf * 128 + ((gf ^ (rf & 7)) << 4);
    const __half* gA = A  + (size_t)(brow + rf) * K + gf * 8;
    const __half* gB = BT + (size_t)(bcol + rf) * K + gf * 8;

    float acc[4][8][4];
    #pragma unroll
    for (int mi = 0; mi < 4; mi++)
        #pragma unroll
        for (int ni = 0; ni < 8; ni++)
            #pragma unroll
            for (int r = 0; r < 4; r++) acc[mi][ni][r] = 0.0f;

    const int nkt = K / TK;

    auto fill = [&](int kt) {
        const int st = kt % NSTAGE;
        uint32_t dA = sb0 + st * STAGE_BYTES;
        uint32_t dB = dA + 16384;
        const __half* ga = gA + kt * TK;
        const __half* gb = gB + kt * TK;
        #pragma unroll
        for (int i = 0; i < 8; i++) {
            uint32_t so = fso + (uint32_t)i * 2048;
            cp16(dA + so, ga + (size_t)i * 16 * K);
            cp16(dB + so, gb + (size_t)i * 16 * K);
        }
        asm volatile("cp.async.commit_group;" ::: "memory");
    };

    // fragment loader for k16-step ks of the current stage
    const int a_row16 = lane & 15;                 // row within 16-row tile
    const int a_hi    = lane >> 4;                 // k-granule half
    const int b_row16 = ((lane >> 4) << 3) + (lane & 7);
    const int b_hi    = (lane >> 3) & 1;
    auto load_frags = [&](uint32_t sA, uint32_t sB, int ks, uint32_t af[4][4], uint32_t bq[4][4]) {
        #pragma unroll
        for (int mi = 0; mi < 4; mi++) {
            int row = wm + mi * 16 + a_row16;
            uint32_t kg = (uint32_t)(ks * 2 + a_hi);
            ldsm4(af[mi], sA + (uint32_t)row * 128 + ((kg ^ (row & 7)) << 4));
        }
        #pragma unroll
        for (int nt = 0; nt < 4; nt++) {
            int nr = wn + nt * 16 + b_row16;
            uint32_t kg = (uint32_t)(ks * 2 + b_hi);
            ldsm4(bq[nt], sB + (uint32_t)nr * 128 + ((kg ^ (nr & 7)) << 4));
        }
    };

    fill(0);
    if (nkt > 1) fill(1);

    uint32_t af[2][4][4], bq[2][4][4];

    for (int kt = 0; kt < nkt; kt++) {
        if (kt + 1 < nkt) asm volatile("cp.async.wait_group 1;" ::: "memory");
        else              asm volatile("cp.async.wait_group 0;" ::: "memory");
        __syncthreads();
        if (kt + 2 < nkt) fill(kt + 2);

        const int st = kt % NSTAGE;
        const uint32_t sA = sb0 + st * STAGE_BYTES;
        const uint32_t sB = sA + 16384;

        load_frags(sA, sB, 0, af[0], bq[0]);
        #pragma unroll
        for (int ks = 0; ks < 4; ks++) {
            const int cur = ks & 1;
            if (ks < 3) load_frags(sA, sB, ks + 1, af[cur ^ 1], bq[cur ^ 1]);
            #pragma unroll
            for (int mi = 0; mi < 4; mi++)
                #pragma unroll
                for (int ni = 0; ni < 8; ni++)
                    mma_f16(acc[mi][ni], af[cur][mi],
                            bq[cur][ni >> 1][(ni & 1) * 2], bq[cur][ni >> 1][(ni & 1) * 2 + 1]);
        }
    }

    const int g = lane >> 2, q = lane & 3;
    #pragma unroll
    for (int ni = 0; ni < 8; ni++) {
        int col = bcol + wn + ni * 8 + q * 2;
        float bb0 = bias[col], bb1 = bias[col + 1];
        #pragma unroll
        for (int mi = 0; mi < 4; mi++) {
            #pragma unroll
            for (int h = 0; h < 2; h++) {
                int row = brow + wm + mi * 16 + g + h * 8;
                size_t off = (size_t)row * N + col;
                float v0 = acc[mi][ni][h * 2 + 0] + bb0;
                float v1 = acc[mi][ni][h * 2 + 1] + bb1;
                if (DO_RES) {
                    __half2 rh = *(const __half2*)(res + off);
                    float2 rf2 = __half22float2(rh);
                    v0 += rf2.x; v1 += rf2.y;
                }
                if (DO_GELU) { v0 = gelu_exact(v0); v1 = gelu_exact(v1); }
                if (sizeof(OT) == 2) {
                    __half2 hv = __floats2half2_rn(v0, v1);
                    *(uint32_t*)((__half*)C + off) = *(uint32_t*)&hv;
                } else {
                    float2 o; o.x = v0; o.y = v1;
                    *(float2*)((float*)C + off) = o;
                }
            }
        }
    }
}

template<bool DO_GELU, bool DO_RES, typename OT>
__global__ void __launch_bounds__(128, 2) hgemm(
    const __half* __restrict__ A, const __half* __restrict__ BT,
    const float* __restrict__ bias, const __half* __restrict__ res,
    OT* __restrict__ C, int N, int K)
{
    extern __shared__ char dsm[];
    hgemm_body<DO_GELU, DO_RES, OT>(A, BT, bias, res, C, N, K,
                                    blockIdx.y * 128, blockIdx.x * 128, dsm);
}

// dual GEMM: flattened 1D grid covering kv-proj + q-proj
struct DP {
    const __half *A1, *B1; const float* bias1; __half* C1; int N1, K1, ntiles1, nx1;
    const __half *A2, *B2; const float* bias2; __half* C2; int N2, K2, nx2;
};
__global__ void __launch_bounds__(128, 2) hgemm_dual(DP p)
{
    extern __shared__ char dsm[];
    int t = blockIdx.x;
    if (t < p.ntiles1) {
        hgemm_body<false, false, __half>(p.A1, p.B1, p.bias1, nullptr, p.C1, p.N1, p.K1,
                                         (t / p.nx1) << 7, (t % p.nx1) << 7, dsm);
    } else {
        t -= p.ntiles1;
        hgemm_body<false, false, __half>(p.A2, p.B2, p.bias2, nullptr, p.C2, p.N2, p.K2,
                                         (t / p.nx2) << 7, (t % p.nx2) << 7, dsm);
    }
}

// ---------------- fp16 flash attention (Q pre-scaled by 1/8 at fill — exact) ----------------
__global__ void __launch_bounds__(256) attn_mma(
    const __half* __restrict__ Q, const __half* __restrict__ KV, __half* __restrict__ O)
{
    extern __shared__ char asm_[];
    const uint32_t Qs = smem_u32(asm_) + AQ_B;
    const uint32_t Ps = smem_u32(asm_) + AP_B;
    const uint32_t Ks = smem_u32(asm_) + AK_B;
    const uint32_t Vs = smem_u32(asm_) + AV_B;

    const int idx = blockIdx.x;
    const int h = idx & 7;
    const int bt = idx >> 3;
    const int b = bt / T_;
    const int tid = threadIdx.x, warp = tid >> 5, lane = tid & 31;
    const int g = lane >> 2, q = lane & 3;
    const int wm = warp * 32;

    {
        const __half* gq = Q + (size_t)(b * NF_) * E_ + h * DH_;
        const __half2 sc = __half2half2(__float2half(0.125f));
        #pragma unroll
        for (int i = tid; i < 256 * 8; i += 256) {
            int r = i >> 3, gg2 = i & 7;
            uint4 v = *(const uint4*)(gq + (size_t)r * E_ + gg2 * 8);
            __half2* hv = (__half2*)&v;
            #pragma unroll
            for (int j = 0; j < 4; j++) hv[j] = __hmul2(hv[j], sc);
            *(uint4*)(asm_ + AQ_B + r * 128 + ((gg2 ^ (r & 7)) << 4)) = v;
        }
    }

    const __half* kvbase = KV + (size_t)bt * NF_ * 1024 + h * DH_;
    auto fillkv = [&](int ch) {
        int st = ch & 1;
        #pragma unroll
        for (int i = tid; i < 64 * 8; i += 256) {
            int r = i >> 3, gk = i & 7;
            const __half* src = kvbase + (size_t)(ch * 64 + r) * 1024 + gk * 8;
            uint32_t so = (uint32_t)(st * 8192 + r * 128 + ((gk ^ (r & 7)) << 4));
            cp16(Ks + so, src);
            cp16(Vs + so, src + 512);
        }
        asm volatile("cp.async.commit_group;" ::: "memory");
    };

    fillkv(0);

    float o[2][8][4];
    #pragma unroll
    for (int mi = 0; mi < 2; mi++)
        #pragma unroll
        for (int nd = 0; nd < 8; nd++)
            #pragma unroll
            for (int r = 0; r < 4; r++) o[mi][nd][r] = 0.0f;
    float mrow[2][2] = {{-1e30f, -1e30f}, {-1e30f, -1e30f}};
    float lrow[2][2] = {{0.0f, 0.0f}, {0.0f, 0.0f}};

    for (int ch = 0; ch < 4; ch++) {
        asm volatile("cp.async.wait_group 0;" ::: "memory");
        __syncthreads();
        if (ch + 1 < 4) fillkv(ch + 1);

        const uint32_t Kst = Ks + (ch & 1) * 8192;
        const uint32_t Vst = Vs + (ch & 1) * 8192;

        float s[2][8][4];
        #pragma unroll
        for (int mi = 0; mi < 2; mi++)
            #pragma unroll
            for (int ni = 0; ni < 8; ni++)
                #pragma unroll
                for (int r = 0; r < 4; r++) s[mi][ni][r] = 0.0f;

        #pragma unroll
        for (int ks = 0; ks < 4; ks++) {
            uint32_t af[2][4], bq[4][4];
            #pragma unroll
            for (int mi = 0; mi < 2; mi++) {
                int row = wm + mi * 16 + (lane & 15);
                uint32_t kg = (uint32_t)(ks * 2 + (lane >> 4));
                ldsm4(af[mi], Qs + (uint32_t)row * 128 + ((kg ^ (row & 7)) << 4));
            }
            #pragma unroll
            for (int nt = 0; nt < 4; nt++) {
                int nr = nt * 16 + ((lane >> 4) << 3) + (lane & 7);
                uint32_t kg = (uint32_t)(ks * 2 + ((lane >> 3) & 1));
                ldsm4(bq[nt], Kst + (uint32_t)nr * 128 + ((kg ^ (nr & 7)) << 4));
            }
            #pragma unroll
            for (int mi = 0; mi < 2; mi++)
                #pragma unroll
                for (int ni = 0; ni < 8; ni++)
                    mma_f16(s[mi][ni], af[mi],
                            bq[ni >> 1][(ni & 1) * 2], bq[ni >> 1][(ni & 1) * 2 + 1]);
        }

        #pragma unroll
        for (int mi = 0; mi < 2; mi++) {
            #pragma unroll
            for (int hh = 0; hh < 2; hh++) {
                float rm = -1e30f;
                #pragma unroll
                for (int ni = 0; ni < 8; ni++)
                    rm = fmaxf(rm, fmaxf(s[mi][ni][hh * 2], s[mi][ni][hh * 2 + 1]));
                rm = fmaxf(rm, __shfl_xor_sync(0xffffffffu, rm, 1));
                rm = fmaxf(rm, __shfl_xor_sync(0xffffffffu, rm, 2));
                float mnew = fmaxf(mrow[mi][hh], rm);
                float alpha = __expf(mrow[mi][hh] - mnew);
                mrow[mi][hh] = mnew;
                float rs = 0.0f;
                #pragma unroll
                for (int ni = 0; ni < 8; ni++) {
                    float p0 = __expf(s[mi][ni][hh * 2]     - mnew);
                    float p1 = __expf(s[mi][ni][hh * 2 + 1] - mnew);
                    rs += p0 + p1;
                    s[mi][ni][hh * 2]     = p0;
                    s[mi][ni][hh * 2 + 1] = p1;
                }
                rs += __shfl_xor_sync(0xffffffffu, rs, 1);
                rs += __shfl_xor_sync(0xffffffffu, rs, 2);
                lrow[mi][hh] = lrow[mi][hh] * alpha + rs;
                #pragma unroll
                for (int nd = 0; nd < 8; nd++) {
                    o[mi][nd][hh * 2]     *= alpha;
                    o[mi][nd][hh * 2 + 1] *= alpha;
                }
            }
        }

        __syncwarp();
        #pragma unroll
        for (int mi = 0; mi < 2; mi++) {
            #pragma unroll
            for (int ni = 0; ni < 8; ni++) {
                int row = wm + mi * 16 + g;
                __half2 p01 = __floats2half2_rn(s[mi][ni][0], s[mi][ni][1]);
                __half2 p23 = __floats2half2_rn(s[mi][ni][2], s[mi][ni][3]);
                *(uint32_t*)(asm_ + AP_B + row * 128 + (((uint32_t)ni ^ (row & 7)) << 4) + q * 4)
                    = *(uint32_t*)&p01;
                int row2 = row + 8;
                *(uint32_t*)(asm_ + AP_B + row2 * 128 + (((uint32_t)ni ^ (row2 & 7)) << 4) + q * 4)
                    = *(uint32_t*)&p23;
            }
        }
        __syncwarp();

        #pragma unroll
        for (int ks = 0; ks < 4; ks++) {
            uint32_t af[2][4], bv[4][4];
            #pragma unroll
            for (int mi = 0; mi < 2; mi++) {
                int row = wm + mi * 16 + (lane & 15);
                uint32_t kg = (uint32_t)(ks * 2 + (lane >> 4));
                ldsm4(af[mi], Ps + (uint32_t)row * 128 + ((kg ^ (row & 7)) << 4));
            }
            #pragma unroll
            for (int nt = 0; nt < 4; nt++) {
                int kr = ks * 16 + (lane & 7) + ((lane >> 3) & 1) * 8;
                uint32_t ng = (uint32_t)(nt * 2 + (lane >> 4));
                ldsm4t(bv[nt], Vst + (uint32_t)kr * 128 + ((ng ^ (kr & 7)) << 4));
            }
            #pragma unroll
            for (int mi = 0; mi < 2; mi++)
                #pragma unroll
                for (int nd = 0; nd < 8; nd++)
                    mma_f16(o[mi][nd], af[mi],
                            bv[nd >> 1][(nd & 1) * 2], bv[nd >> 1][(nd & 1) * 2 + 1]);
        }
        __syncwarp();
    }

    #pragma unroll
    for (int mi = 0; mi < 2; mi++) {
        #pragma unroll
        for (int hh = 0; hh < 2; hh++) {
            float inv = 1.0f / lrow[mi][hh];
            int row = wm + mi * 16 + g + hh * 8;
            __half* orow = O + ((size_t)bt * NF_ + row) * E_ + h * DH_;
            #pragma unroll
            for (int nd = 0; nd < 8; nd++) {
                __half2 ov = __floats2half2_rn(o[mi][nd][hh * 2] * inv,
                                               o[mi][nd][hh * 2 + 1] * inv);
                *(uint32_t*)(orow + nd * 8 + 2 * q) = *(uint32_t*)&ov;
            }
        }
    }
}

// ---------------- host ----------------
extern "C" void kernel_launch(void* const* d_in, const int* in_sizes, int n_in,
                              void* d_out, int out_size)
{
    const float* inputs  = (const float*)d_in[0];
    const float* wq      = (const float*)d_in[1];
    const float* wk      = (const float*)d_in[2];
    const float* wv      = (const float*)d_in[3];
    const float* bq      = (const float*)d_in[4];
    const float* bk      = (const float*)d_in[5];
    const float* bv      = (const float*)d_in[6];
    const float* wo      = (const float*)d_in[7];
    const float* bo      = (const float*)d_in[8];
    const float* lnq_g   = (const float*)d_in[9];
    const float* lnq_b   = (const float*)d_in[10];
    const float* lnkv_g  = (const float*)d_in[11];
    const float* lnkv_b  = (const float*)d_in[12];
    const float* mlpq_w1 = (const float*)d_in[13];
    const float* mlpq_b1 = (const float*)d_in[14];
    const float* mlpq_w2 = (const float*)d_in[15];
    const float* mlpq_b2 = (const float*)d_in[16];
    const float* resln_g = (const float*)d_in[17];
    const float* resln_b = (const float*)d_in[18];
    const float* ln2_g   = (const float*)d_in[19];
    const float* ln2_b   = (const float*)d_in[20];
    const float* mlp_w1  = (const float*)d_in[21];
    const float* mlp_b1  = (const float*)d_in[22];
    const float* mlp_w2  = (const float*)d_in[23];
    const float* mlp_b2  = (const float*)d_in[24];
    float* out = (float*)d_out;

    __half *qln, *q, *kvln, *kv, *t1h, *t2h, *hid, *wtA, *wtB, *wqT;
    float *bkvC;
    cudaGetSymbolAddress((void**)&qln,  g_qln);
    cudaGetSymbolAddress((void**)&q,    g_q);
    cudaGetSymbolAddress((void**)&kvln, g_kvln);
    cudaGetSymbolAddress((void**)&kv,   g_kv);
    cudaGetSymbolAddress((void**)&t1h,  g_t1h);
    cudaGetSymbolAddress((void**)&t2h,  g_t2h);
    cudaGetSymbolAddress((void**)&hid,  g_hid);
    cudaGetSymbolAddress((void**)&wtA,  g_wtA);
    cudaGetSymbolAddress((void**)&wtB,  g_wtB);
    cudaGetSymbolAddress((void**)&wqT,  g_wqT);
    cudaGetSymbolAddress((void**)&bkvC, g_bkv);

    __half* wkvT = wtA;
    __half* woT  = wtA + (size_t)2 * E_ * E_;
    __half* mq1T = wtB;
    __half* mq2T = wtB + (size_t)E_ * M_;
    __half* m1T  = wtB + (size_t)2 * E_ * M_;
    __half* m2T  = wtB + (size_t)3 * E_ * M_;

    cudaFuncSetAttribute(hgemm<false,false,__half>, cudaFuncAttributeMaxDynamicSharedMemorySize, SMEM_TOTAL);
    cudaFuncSetAttribute(hgemm<true ,false,__half>, cudaFuncAttributeMaxDynamicSharedMemorySize, SMEM_TOTAL);
    cudaFuncSetAttribute(hgemm<false,true ,__half>, cudaFuncAttributeMaxDynamicSharedMemorySize, SMEM_TOTAL);
    cudaFuncSetAttribute(hgemm<false,false,float >, cudaFuncAttributeMaxDynamicSharedMemorySize, SMEM_TOTAL);
    cudaFuncSetAttribute(hgemm_dual, cudaFuncAttributeMaxDynamicSharedMemorySize, SMEM_TOTAL);
    cudaFuncSetAttribute(attn_mma, cudaFuncAttributeMaxDynamicSharedMemorySize, ATTN_SMEM);

    PreDesc pd;
    int off = 0;
    auto seg = [&](int i, const float* W, __half* WT, int K, int N) {
        pd.s[i].W = W; pd.s[i].WT = WT; pd.s[i].K = K; pd.s[i].N = N; pd.s[i].blk0 = off;
        off += (N / 32) * (K / 32);
    };
    seg(0, wk,      wkvT,                    E_, E_);
    seg(1, wv,      wkvT + (size_t)E_ * E_,  E_, E_);
    seg(2, wq,      wqT,                     E_, E_);
    seg(3, wo,      woT,                     E_, E_);
    seg(4, mlpq_w1, mq1T,                    E_, M_);
    seg(5, mlpq_w2, mq2T,                    M_, E_);
    seg(6, mlp_w1,  m1T,                     E_, M_);
    seg(7, mlp_w2,  m2T,                     M_, E_);
    pd.bk = bk; pd.bv = bv; pd.bkvO = bkvC;
    pd.X = inputs; pd.gq = lnq_g; pd.bq = lnq_b; pd.gkv = lnkv_g; pd.bkvLN = lnkv_b;
    pd.out_q = qln; pd.out_kv = kvln;
    const int nblk_t = off;                         // 5120

    DP dp;
    dp.A1 = kvln; dp.B1 = wkvT; dp.bias1 = bkvC; dp.C1 = kv;
    dp.N1 = 1024; dp.K1 = E_; dp.nx1 = 1024 / 128;
    dp.ntiles1 = (ROWS_KV / 128) * dp.nx1;          // 3968
    dp.A2 = qln; dp.B2 = wqT; dp.bias2 = bq; dp.C2 = q;
    dp.N2 = E_; dp.K2 = E_; dp.nx2 = E_ / 128;
    const int ntiles2 = (ROWS_Q / 128) * dp.nx2;    // 16

    // 1) fused pre-work
    pre_all<<<nblk_t + 1 + B_ * HW_ * NF_, 256>>>(pd, nblk_t);
    // 2) kv + q projections in one launch
    hgemm_dual<<<dp.ntiles1 + ntiles2, 128, SMEM_TOTAL>>>(dp);
    // 3) attention -> t1h
    attn_mma<<<B_ * T_ * H_, 256, ATTN_SMEM>>>(q, kv, t1h);
    // 4) out projection: t1h -> t2h
    hgemm<false,false,__half><<<dim3(E_/128, ROWS_KV/128), 128, SMEM_TOTAL>>>(t1h, woT, bo, nullptr, t2h, E_, E_);
    // 5-6) mlp_q: t2h -> hid (GELU) -> t1h (fp16, + residual kvln)
    hgemm<true ,false,__half><<<dim3(M_/128, ROWS_KV/128), 128, SMEM_TOTAL>>>(t2h, mq1T, mlpq_b1, nullptr, hid, M_, E_);
    hgemm<false,true ,__half><<<dim3(E_/128, ROWS_KV/128), 128, SMEM_TOTAL>>>(hid, mq2T, mlpq_b2, kvln,  t1h, E_, M_);
    // 7) res_ln + ln_2 fused: t1h -> t2h
    dual_ln_kernel<<<ROWS_KV, 128>>>(t1h, resln_g, resln_b, ln2_g, ln2_b, t2h);
    // 8-9) final MLP: t2h -> hid (GELU) -> out (fp32)
    hgemm<true ,false,__half><<<dim3(M_/128, ROWS_KV/128), 128, SMEM_TOTAL>>>(t2h, m1T, mlp_b1, nullptr, hid, M_, E_);
    hgemm<false,false,float ><<<dim3(E_/128, ROWS_KV/128), 128, SMEM_TOTAL>>>(hid, m2T, mlp_b2, nullptr, out, E_, M_);
}

// round 16
// speedup vs baseline: 1.0289x; 1.0289x over previous
#include <cuda_runtime.h>
#include <cuda_fp16.h>
#include <math.h>
#include <stdint.h>

// Problem shapes
#define B_   8
#define HW_  32
#define T_   31
#define NF_  256
#define E_   512
#define M_   2048
#define H_   8
#define DH_  64

#define ROWS_Q   (B_ * NF_)            // 2048
#define ROWS_KV  (B_ * T_ * NF_)       // 63488

// hgemm tiling: CTA 128x128, K-chunk 64 (fp16), 3-stage, 4 warps of 64x64
#define TK 64
#define NSTAGE 3
#define STAGE_BYTES 32768
#define SMEM_TOTAL (NSTAGE * STAGE_BYTES)   // 98304

// Attention smem (bytes)
#define AQ_B 0
#define AP_B 32768
#define AK_B 65536
#define AV_B 81920
#define ATTN_SMEM 98304

// ---------------- static scratch ----------------
__device__ __half g_qln [ (size_t)ROWS_Q  * E_ ];
__device__ __half g_q   [ (size_t)ROWS_Q  * E_ ];
__device__ __half g_kvln[ (size_t)ROWS_KV * E_ ];
__device__ __half g_kv  [ (size_t)ROWS_KV * 1024 ];
__device__ __half g_t1h [ (size_t)ROWS_KV * E_ ];
__device__ __half g_t2h [ (size_t)ROWS_KV * E_ ];
__device__ __half g_hid [ (size_t)ROWS_KV * M_ ];
__device__ __half g_wtA [ (size_t)4 * E_ * E_ ];
__device__ __half g_wtB [ (size_t)4 * E_ * M_ ];
__device__ __half g_wqT [ (size_t)E_ * E_ ];
__device__ float  g_bkv [ 1024 ];

// ---------------- helpers ----------------
__device__ __forceinline__ float gelu_exact(float x) {
    return 0.5f * x * (1.0f + erff(x * 0.70710678118654752f));
}
__device__ __forceinline__ uint32_t smem_u32(const void* p) {
    uint32_t a;
    asm("{ .reg .u64 t; cvta.to.shared.u64 t, %1; cvt.u32.u64 %0, t; }" : "=r"(a) : "l"(p));
    return a;
}
__device__ __forceinline__ void cp16(uint32_t s, const void* g) {
    asm volatile("cp.async.cg.shared.global [%0], [%1], 16;" :: "r"(s), "l"(g));
}
__device__ __forceinline__ void ldsm4(uint32_t* r, uint32_t a) {
    asm volatile("ldmatrix.sync.aligned.m8n8.x4.shared.b16 {%0,%1,%2,%3}, [%4];"
        : "=r"(r[0]), "=r"(r[1]), "=r"(r[2]), "=r"(r[3]) : "r"(a));
}
__device__ __forceinline__ void ldsm4t(uint32_t* r, uint32_t a) {
    asm volatile("ldmatrix.sync.aligned.m8n8.x4.trans.shared.b16 {%0,%1,%2,%3}, [%4];"
        : "=r"(r[0]), "=r"(r[1]), "=r"(r[2]), "=r"(r[3]) : "r"(a));
}
__device__ __forceinline__ void mma_f16(float* d, const uint32_t* a, uint32_t b0, uint32_t b1) {
    asm volatile(
        "mma.sync.aligned.m16n8k16.row.col.f32.f16.f16.f32 "
        "{%0,%1,%2,%3}, {%4,%5,%6,%7}, {%8,%9}, {%0,%1,%2,%3};"
        : "+f"(d[0]), "+f"(d[1]), "+f"(d[2]), "+f"(d[3])
        : "r"(a[0]), "r"(a[1]), "r"(a[2]), "r"(a[3]), "r"(b0), "r"(b1));
}

__device__ __forceinline__ float blk_sum4(float v, float* sb) {   // 128 threads
    #pragma unroll
    for (int o = 16; o; o >>= 1) v += __shfl_xor_sync(0xffffffffu, v, o);
    if ((threadIdx.x & 31) == 0) sb[threadIdx.x >> 5] = v;
    __syncthreads();
    float r = sb[0] + sb[1] + sb[2] + sb[3];
    __syncthreads();
    return r;
}
__device__ __forceinline__ float blk_sum8(float v, float* sb) {   // 256 threads
    #pragma unroll
    for (int o = 16; o; o >>= 1) v += __shfl_xor_sync(0xffffffffu, v, o);
    if ((threadIdx.x & 31) == 0) sb[threadIdx.x >> 5] = v;
    __syncthreads();
    float r = sb[0] + sb[1] + sb[2] + sb[3] + sb[4] + sb[5] + sb[6] + sb[7];
    __syncthreads();
    return r;
}

// ---------------- fused pre-work: 8 weight transposes + bias concat + input LN ----------------
struct TSeg { const float* W; __half* WT; int K; int N; int blk0; };
struct PreDesc {
    TSeg s[8];
    const float *bk, *bv; float* bkvO;
    const float *X, *gq, *bq, *gkv, *bkvLN;
    __half *out_q, *out_kv;
};

__global__ void __launch_bounds__(256) pre_all(PreDesc d, int nblk_t)
{
    __shared__ float shm[32 * 33];
    int blk = blockIdx.x;

    if (blk < nblk_t) {                                  // --- transpose segment ---
        float (*t)[33] = (float(*)[33])shm;
        int si = 0;
        #pragma unroll
        for (int j = 1; j < 8; j++) if (blk >= d.s[j].blk0) si = j;
        const TSeg sg = d.s[si];
        int b = blk - sg.blk0;
        int nx = sg.N >> 5;
        int n0 = (b % nx) * 32, k0 = (b / nx) * 32;
        int tx = threadIdx.x & 31, ty = threadIdx.x >> 5;
        #pragma unroll
        for (int j = 0; j < 32; j += 8)
            t[ty + j][tx] = sg.W[(size_t)(k0 + ty + j) * sg.N + n0 + tx];
        __syncthreads();
        #pragma unroll
        for (int j = 0; j < 32; j += 8)
            sg.WT[(size_t)(n0 + ty + j) * sg.K + k0 + tx] = __float2half_rn(t[tx][ty + j]);
        return;
    }
    if (blk == nblk_t) {                                 // --- bias concat ---
        int i = threadIdx.x;
        #pragma unroll
        for (int j = 0; j < 4; j++) {
            int idx = i + j * 256;
            d.bkvO[idx] = (idx < 512) ? d.bk[idx] : d.bv[idx - 512];
        }
        return;
    }

    // --- input LN row ---
    int r = blk - nblk_t - 1;                            // 0 .. 8191
    int b = r >> 13;
    int t = (r >> 8) & 31;
    int n = r & 255;
    int c = threadIdx.x * 2;

    float2 xv = *(const float2*)(d.X + (size_t)r * E_ + c);
    float s = xv.x + xv.y;
    float mean = blk_sum8(s, shm) * (1.0f / E_);
    float d0 = xv.x - mean, d1 = xv.y - mean;
    float var = blk_sum8(d0 * d0 + d1 * d1, shm) * (1.0f / E_);
    float rs = rsqrtf(var + 1e-6f);

    const float *g, *be; __half* dst;
    if (t == 0) { g = d.gq;  be = d.bq;    dst = d.out_q  + ((size_t)(b * NF_ + n)) * E_; }
    else        { g = d.gkv; be = d.bkvLN; dst = d.out_kv + ((size_t)((b * T_ + (t - 1)) * NF_ + n)) * E_; }

    float2 gg = *(const float2*)(g + c);
    float2 bb = *(const float2*)(be + c);
    __half2 h = __floats2half2_rn(d0 * rs * gg.x + bb.x, d1 * rs * gg.y + bb.y);
    *(uint32_t*)(dst + c) = *(uint32_t*)&h;
}

// ---------------- fused double LayerNorm: fp16 in -> fp16 out ----------------
__global__ void __launch_bounds__(128) dual_ln_kernel(
    const __half* __restrict__ X,
    const float* __restrict__ g1, const float* __restrict__ b1,
    const float* __restrict__ g2, const float* __restrict__ b2,
    __half* __restrict__ Y)
{
    __shared__ float sb[4];
    size_t r = blockIdx.x;
    int c = threadIdx.x * 4;
    uint2 xu = *(const uint2*)(X + r * E_ + c);
    float2 xa = __half22float2(*(__half2*)&xu.x);
    float2 xb = __half22float2(*(__half2*)&xu.y);

    float s = xa.x + xa.y + xb.x + xb.y;
    float mean = blk_sum4(s, sb) * (1.0f / E_);
    float d0 = xa.x - mean, d1 = xa.y - mean, d2 = xb.x - mean, d3 = xb.y - mean;
    float var = blk_sum4(d0*d0 + d1*d1 + d2*d2 + d3*d3, sb) * (1.0f / E_);
    float rs = rsqrtf(var + 1e-6f);

    float4 gg = *(const float4*)(g1 + c);
    float4 bb = *(const float4*)(b1 + c);
    float y0 = d0 * rs * gg.x + bb.x;
    float y1 = d1 * rs * gg.y + bb.y;
    float y2 = d2 * rs * gg.z + bb.z;
    float y3 = d3 * rs * gg.w + bb.w;

    float s2 = y0 + y1 + y2 + y3;
    float mean2 = blk_sum4(s2, sb) * (1.0f / E_);
    float e0 = y0 - mean2, e1 = y1 - mean2, e2 = y2 - mean2, e3 = y3 - mean2;
    float var2 = blk_sum4(e0*e0 + e1*e1 + e2*e2 + e3*e3, sb) * (1.0f / E_);
    float rs2 = rsqrtf(var2 + 1e-6f);

    float4 gg2 = *(const float4*)(g2 + c);
    float4 bb2 = *(const float4*)(b2 + c);
    __half2 h0 = __floats2half2_rn(e0 * rs2 * gg2.x + bb2.x, e1 * rs2 * gg2.y + bb2.y);
    __half2 h1 = __floats2half2_rn(e2 * rs2 * gg2.z + bb2.z, e3 * rs2 * gg2.w + bb2.w);
    uint2 u; u.x = *(uint32_t*)&h0; u.y = *(uint32_t*)&h1;
    *(uint2*)(Y + r * E_ + c) = u;
}

// ---------------- fp16 mma GEMM body (R12/R14-proven: 128 threads, 4 warps of 64x64) ----------------
template<bool DO_GELU, bool DO_RES, typename OT>
__device__ __forceinline__ void hgemm_body(
    const __half* __restrict__ A, const __half* __restrict__ BT,
    const float* __restrict__ bias, const __half* __restrict__ res,
    OT* __restrict__ C, int N, int K, int brow, int bcol, char* dsm)
{
    const uint32_t sb0 = smem_u32(dsm);
    const int tid = threadIdx.x, warp = tid >> 5, lane = tid & 31;
    const int wm = (warp >> 1) * 64, wn = (warp & 1) * 64;

    const int rf = tid >> 3, gf = tid & 7;
    const uint32_t fso = (uint32_t)rf * 128 + ((gf ^ (rf & 7)) << 4);
    const __half* gA = A  + (size_t)(brow + rf) * K + gf * 8;
    const __half* gB = BT + (size_t)(bcol + rf) * K + gf * 8;

    float acc[4][8][4];
    #pragma unroll
    for (int mi = 0; mi < 4; mi++)
        #pragma unroll
        for (int ni = 0; ni < 8; ni++)
            #pragma unroll
            for (int r = 0; r < 4; r++) acc[mi][ni][r] = 0.0f;

    const int nkt = K / TK;

    auto fill = [&](int kt) {
        const int st = kt % NSTAGE;
        uint32_t dA = sb0 + st * STAGE_BYTES;
        uint32_t dB = dA + 16384;
        const __half* ga = gA + kt * TK;
        const __half* gb = gB + kt * TK;
        #pragma unroll
        for (int i = 0; i < 8; i++) {
            uint32_t so = fso + (uint32_t)i * 2048;
            cp16(dA + so, ga + (size_t)i * 16 * K);
            cp16(dB + so, gb + (size_t)i * 16 * K);
        }
        asm volatile("cp.async.commit_group;" ::: "memory");
    };

    fill(0);
    if (nkt > 1) fill(1);

    for (int kt = 0; kt < nkt; kt++) {
        if (kt + 1 < nkt) asm volatile("cp.async.wait_group 1;" ::: "memory");
        else              asm volatile("cp.async.wait_group 0;" ::: "memory");
        __syncthreads();
        if (kt + 2 < nkt) fill(kt + 2);

        const int st = kt % NSTAGE;
        const uint32_t sA = sb0 + st * STAGE_BYTES;
        const uint32_t sB = sA + 16384;

        #pragma unroll
        for (int ks = 0; ks < 4; ks++) {
            uint32_t af[4][4], bq[4][4];
            #pragma unroll
            for (int mi = 0; mi < 4; mi++) {
                int row = wm + mi * 16 + (lane & 15);
                uint32_t kg = (uint32_t)(ks * 2 + (lane >> 4));
                ldsm4(af[mi], sA + (uint32_t)row * 128 + ((kg ^ (row & 7)) << 4));
            }
            #pragma unroll
            for (int nt = 0; nt < 4; nt++) {
                int nr = wn + nt * 16 + ((lane >> 4) << 3) + (lane & 7);
                uint32_t kg = (uint32_t)(ks * 2 + ((lane >> 3) & 1));
                ldsm4(bq[nt], sB + (uint32_t)nr * 128 + ((kg ^ (nr & 7)) << 4));
            }
            #pragma unroll
            for (int mi = 0; mi < 4; mi++)
                #pragma unroll
                for (int ni = 0; ni < 8; ni++)
                    mma_f16(acc[mi][ni], af[mi],
                            bq[ni >> 1][(ni & 1) * 2], bq[ni >> 1][(ni & 1) * 2 + 1]);
        }
    }

    const int g = lane >> 2, q = lane & 3;
    #pragma unroll
    for (int ni = 0; ni < 8; ni++) {
        int col = bcol + wn + ni * 8 + q * 2;
        float bb0 = bias[col], bb1 = bias[col + 1];
        #pragma unroll
        for (int mi = 0; mi < 4; mi++) {
            #pragma unroll
            for (int h = 0; h < 2; h++) {
                int row = brow + wm + mi * 16 + g + h * 8;
                size_t off = (size_t)row * N + col;
                float v0 = acc[mi][ni][h * 2 + 0] + bb0;
                float v1 = acc[mi][ni][h * 2 + 1] + bb1;
                if (DO_RES) {
                    __half2 rh = *(const __half2*)(res + off);
                    float2 rf2 = __half22float2(rh);
                    v0 += rf2.x; v1 += rf2.y;
                }
                if (DO_GELU) { v0 = gelu_exact(v0); v1 = gelu_exact(v1); }
                if (sizeof(OT) == 2) {
                    __half2 hv = __floats2half2_rn(v0, v1);
                    *(uint32_t*)((__half*)C + off) = *(uint32_t*)&hv;
                } else {
                    float2 o; o.x = v0; o.y = v1;
                    *(float2*)((float*)C + off) = o;
                }
            }
        }
    }
}

template<bool DO_GELU, bool DO_RES, typename OT>
__global__ void __launch_bounds__(128, 2) hgemm(
    const __half* __restrict__ A, const __half* __restrict__ BT,
    const float* __restrict__ bias, const __half* __restrict__ res,
    OT* __restrict__ C, int N, int K)
{
    extern __shared__ char dsm[];
    hgemm_body<DO_GELU, DO_RES, OT>(A, BT, bias, res, C, N, K,
                                    blockIdx.y * 128, blockIdx.x * 128, dsm);
}

// dual GEMM: flattened 1D grid covering kv-proj + q-proj
struct DP {
    const __half *A1, *B1; const float* bias1; __half* C1; int N1, K1, ntiles1, nx1;
    const __half *A2, *B2; const float* bias2; __half* C2; int N2, K2, nx2;
};
__global__ void __launch_bounds__(128, 2) hgemm_dual(DP p)
{
    extern __shared__ char dsm[];
    int t = blockIdx.x;
    if (t < p.ntiles1) {
        hgemm_body<false, false, __half>(p.A1, p.B1, p.bias1, nullptr, p.C1, p.N1, p.K1,
                                         (t / p.nx1) << 7, (t % p.nx1) << 7, dsm);
    } else {
        t -= p.ntiles1;
        hgemm_body<false, false, __half>(p.A2, p.B2, p.bias2, nullptr, p.C2, p.N2, p.K2,
                                         (t / p.nx2) << 7, (t % p.nx2) << 7, dsm);
    }
}

// ---------------- fp16 flash attention (Q pre-scaled by 1/8 at fill — exact) ----------------
__global__ void __launch_bounds__(256) attn_mma(
    const __half* __restrict__ Q, const __half* __restrict__ KV, __half* __restrict__ O)
{
    extern __shared__ char asm_[];
    const uint32_t Qs = smem_u32(asm_) + AQ_B;
    const uint32_t Ps = smem_u32(asm_) + AP_B;
    const uint32_t Ks = smem_u32(asm_) + AK_B;
    const uint32_t Vs = smem_u32(asm_) + AV_B;

    const int idx = blockIdx.x;
    const int h = idx & 7;
    const int bt = idx >> 3;
    const int b = bt / T_;
    const int tid = threadIdx.x, warp = tid >> 5, lane = tid & 31;
    const int g = lane >> 2, q = lane & 3;
    const int wm = warp * 32;

    {
        const __half* gq = Q + (size_t)(b * NF_) * E_ + h * DH_;
        const __half2 sc = __half2half2(__float2half(0.125f));
        #pragma unroll
        for (int i = tid; i < 256 * 8; i += 256) {
            int r = i >> 3, gg2 = i & 7;
            uint4 v = *(const uint4*)(gq + (size_t)r * E_ + gg2 * 8);
            __half2* hv = (__half2*)&v;
            #pragma unroll
            for (int j = 0; j < 4; j++) hv[j] = __hmul2(hv[j], sc);
            *(uint4*)(asm_ + AQ_B + r * 128 + ((gg2 ^ (r & 7)) << 4)) = v;
        }
    }

    const __half* kvbase = KV + (size_t)bt * NF_ * 1024 + h * DH_;
    auto fillkv = [&](int ch) {
        int st = ch & 1;
        #pragma unroll
        for (int i = tid; i < 64 * 8; i += 256) {
            int r = i >> 3, gk = i & 7;
            const __half* src = kvbase + (size_t)(ch * 64 + r) * 1024 + gk * 8;
            uint32_t so = (uint32_t)(st * 8192 + r * 128 + ((gk ^ (r & 7)) << 4));
            cp16(Ks + so, src);
            cp16(Vs + so, src + 512);
        }
        asm volatile("cp.async.commit_group;" ::: "memory");
    };

    fillkv(0);

    float o[2][8][4];
    #pragma unroll
    for (int mi = 0; mi < 2; mi++)
        #pragma unroll
        for (int nd = 0; nd < 8; nd++)
            #pragma unroll
            for (int r = 0; r < 4; r++) o[mi][nd][r] = 0.0f;
    float mrow[2][2] = {{-1e30f, -1e30f}, {-1e30f, -1e30f}};
    float lrow[2][2] = {{0.0f, 0.0f}, {0.0f, 0.0f}};

    for (int ch = 0; ch < 4; ch++) {
        asm volatile("cp.async.wait_group 0;" ::: "memory");
        __syncthreads();
        if (ch + 1 < 4) fillkv(ch + 1);

        const uint32_t Kst = Ks + (ch & 1) * 8192;
        const uint32_t Vst = Vs + (ch & 1) * 8192;

        float s[2][8][4];
        #pragma unroll
        for (int mi = 0; mi < 2; mi++)
            #pragma unroll
            for (int ni = 0; ni < 8; ni++)
                #pragma unroll
                for (int r = 0; r < 4; r++) s[mi][ni][r] = 0.0f;

        #pragma unroll
        for (int ks = 0; ks < 4; ks++) {
            uint32_t af[2][4], bq[4][4];
            #pragma unroll
            for (int mi = 0; mi < 2; mi++) {
                int row = wm + mi * 16 + (lane & 15);
                uint32_t kg = (uint32_t)(ks * 2 + (lane >> 4));
                ldsm4(af[mi], Qs + (uint32_t)row * 128 + ((kg ^ (row & 7)) << 4));
            }
            #pragma unroll
            for (int nt = 0; nt < 4; nt++) {
                int nr = nt * 16 + ((lane >> 4) << 3) + (lane & 7);
                uint32_t kg = (uint32_t)(ks * 2 + ((lane >> 3) & 1));
                ldsm4(bq[nt], Kst + (uint32_t)nr * 128 + ((kg ^ (nr & 7)) << 4));
            }
            #pragma unroll
            for (int mi = 0; mi < 2; mi++)
                #pragma unroll
                for (int ni = 0; ni < 8; ni++)
                    mma_f16(s[mi][ni], af[mi],
                            bq[ni >> 1][(ni & 1) * 2], bq[ni >> 1][(ni & 1) * 2 + 1]);
        }

        #pragma unroll
        for (int mi = 0; mi < 2; mi++) {
            #pragma unroll
            for (int hh = 0; hh < 2; hh++) {
                float rm = -1e30f;
                #pragma unroll
                for (int ni = 0; ni < 8; ni++)
                    rm = fmaxf(rm, fmaxf(s[mi][ni][hh * 2], s[mi][ni][hh * 2 + 1]));
                rm = fmaxf(rm, __shfl_xor_sync(0xffffffffu, rm, 1));
                rm = fmaxf(rm, __shfl_xor_sync(0xffffffffu, rm, 2));
                float mnew = fmaxf(mrow[mi][hh], rm);
                float alpha = __expf(mrow[mi][hh] - mnew);
                mrow[mi][hh] = mnew;
                float rs = 0.0f;
                #pragma unroll
                for (int ni = 0; ni < 8; ni++) {
                    float p0 = __expf(s[mi][ni][hh * 2]     - mnew);
                    float p1 = __expf(s[mi][ni][hh * 2 + 1] - mnew);
                    rs += p0 + p1;
                    s[mi][ni][hh * 2]     = p0;
                    s[mi][ni][hh * 2 + 1] = p1;
                }
                rs += __shfl_xor_sync(0xffffffffu, rs, 1);
                rs += __shfl_xor_sync(0xffffffffu, rs, 2);
                lrow[mi][hh] = lrow[mi][hh] * alpha + rs;
                #pragma unroll
                for (int nd = 0; nd < 8; nd++) {
                    o[mi][nd][hh * 2]     *= alpha;
                    o[mi][nd][hh * 2 + 1] *= alpha;
                }
            }
        }

        __syncwarp();
        #pragma unroll
        for (int mi = 0; mi < 2; mi++) {
            #pragma unroll
            for (int ni = 0; ni < 8; ni++) {
                int row = wm + mi * 16 + g;
                __half2 p01 = __floats2half2_rn(s[mi][ni][0], s[mi][ni][1]);
                __half2 p23 = __floats2half2_rn(s[mi][ni][2], s[mi][ni][3]);
                *(uint32_t*)(asm_ + AP_B + row * 128 + (((uint32_t)ni ^ (row & 7)) << 4) + q * 4)
                    = *(uint32_t*)&p01;
                int row2 = row + 8;
                *(uint32_t*)(asm_ + AP_B + row2 * 128 + (((uint32_t)ni ^ (row2 & 7)) << 4) + q * 4)
                    = *(uint32_t*)&p23;
            }
        }
        __syncwarp();

        #pragma unroll
        for (int ks = 0; ks < 4; ks++) {
            uint32_t af[2][4], bv[4][4];
            #pragma unroll
            for (int mi = 0; mi < 2; mi++) {
                int row = wm + mi * 16 + (lane & 15);
                uint32_t kg = (uint32_t)(ks * 2 + (lane >> 4));
                ldsm4(af[mi], Ps + (uint32_t)row * 128 + ((kg ^ (row & 7)) << 4));
            }
            #pragma unroll
            for (int nt = 0; nt < 4; nt++) {
                int kr = ks * 16 + (lane & 7) + ((lane >> 3) & 1) * 8;
                uint32_t ng = (uint32_t)(nt * 2 + (lane >> 4));
                ldsm4t(bv[nt], Vst + (uint32_t)kr * 128 + ((ng ^ (kr & 7)) << 4));
            }
            #pragma unroll
            for (int mi = 0; mi < 2; mi++)
                #pragma unroll
                for (int nd = 0; nd < 8; nd++)
                    mma_f16(o[mi][nd], af[mi],
                            bv[nd >> 1][(nd & 1) * 2], bv[nd >> 1][(nd & 1) * 2 + 1]);
        }
        __syncwarp();
    }

    #pragma unroll
    for (int mi = 0; mi < 2; mi++) {
        #pragma unroll
        for (int hh = 0; hh < 2; hh++) {
            float inv = 1.0f / lrow[mi][hh];
            int row = wm + mi * 16 + g + hh * 8;
            __half* orow = O + ((size_t)bt * NF_ + row) * E_ + h * DH_;
            #pragma unroll
            for (int nd = 0; nd < 8; nd++) {
                __half2 ov = __floats2half2_rn(o[mi][nd][hh * 2] * inv,
                                               o[mi][nd][hh * 2 + 1] * inv);
                *(uint32_t*)(orow + nd * 8 + 2 * q) = *(uint32_t*)&ov;
            }
        }
    }
}

// ---------------- host ----------------
extern "C" void kernel_launch(void* const* d_in, const int* in_sizes, int n_in,
                              void* d_out, int out_size)
{
    const float* inputs  = (const float*)d_in[0];
    const float* wq      = (const float*)d_in[1];
    const float* wk      = (const float*)d_in[2];
    const float* wv      = (const float*)d_in[3];
    const float* bq      = (const float*)d_in[4];
    const float* bk      = (const float*)d_in[5];
    const float* bv      = (const float*)d_in[6];
    const float* wo      = (const float*)d_in[7];
    const float* bo      = (const float*)d_in[8];
    const float* lnq_g   = (const float*)d_in[9];
    const float* lnq_b   = (const float*)d_in[10];
    const float* lnkv_g  = (const float*)d_in[11];
    const float* lnkv_b  = (const float*)d_in[12];
    const float* mlpq_w1 = (const float*)d_in[13];
    const float* mlpq_b1 = (const float*)d_in[14];
    const float* mlpq_w2 = (const float*)d_in[15];
    const float* mlpq_b2 = (const float*)d_in[16];
    const float* resln_g = (const float*)d_in[17];
    const float* resln_b = (const float*)d_in[18];
    const float* ln2_g   = (const float*)d_in[19];
    const float* ln2_b   = (const float*)d_in[20];
    const float* mlp_w1  = (const float*)d_in[21];
    const float* mlp_b1  = (const float*)d_in[22];
    const float* mlp_w2  = (const float*)d_in[23];
    const float* mlp_b2  = (const float*)d_in[24];
    float* out = (float*)d_out;

    __half *qln, *q, *kvln, *kv, *t1h, *t2h, *hid, *wtA, *wtB, *wqT;
    float *bkvC;
    cudaGetSymbolAddress((void**)&qln,  g_qln);
    cudaGetSymbolAddress((void**)&q,    g_q);
    cudaGetSymbolAddress((void**)&kvln, g_kvln);
    cudaGetSymbolAddress((void**)&kv,   g_kv);
    cudaGetSymbolAddress((void**)&t1h,  g_t1h);
    cudaGetSymbolAddress((void**)&t2h,  g_t2h);
    cudaGetSymbolAddress((void**)&hid,  g_hid);
    cudaGetSymbolAddress((void**)&wtA,  g_wtA);
    cudaGetSymbolAddress((void**)&wtB,  g_wtB);
    cudaGetSymbolAddress((void**)&wqT,  g_wqT);
    cudaGetSymbolAddress((void**)&bkvC, g_bkv);

    __half* wkvT = wtA;
    __half* woT  = wtA + (size_t)2 * E_ * E_;
    __half* mq1T = wtB;
    __half* mq2T = wtB + (size_t)E_ * M_;
    __half* m1T  = wtB + (size_t)2 * E_ * M_;
    __half* m2T  = wtB + (size_t)3 * E_ * M_;

    cudaFuncSetAttribute(hgemm<false,false,__half>, cudaFuncAttributeMaxDynamicSharedMemorySize, SMEM_TOTAL);
    cudaFuncSetAttribute(hgemm<true ,false,__half>, cudaFuncAttributeMaxDynamicSharedMemorySize, SMEM_TOTAL);
    cudaFuncSetAttribute(hgemm<false,true ,__half>, cudaFuncAttributeMaxDynamicSharedMemorySize, SMEM_TOTAL);
    cudaFuncSetAttribute(hgemm<false,false,float >, cudaFuncAttributeMaxDynamicSharedMemorySize, SMEM_TOTAL);
    cudaFuncSetAttribute(hgemm_dual, cudaFuncAttributeMaxDynamicSharedMemorySize, SMEM_TOTAL);
    cudaFuncSetAttribute(attn_mma, cudaFuncAttributeMaxDynamicSharedMemorySize, ATTN_SMEM);

    PreDesc pd;
    int off = 0;
    auto seg = [&](int i, const float* W, __half* WT, int K, int N) {
        pd.s[i].W = W; pd.s[i].WT = WT; pd.s[i].K = K; pd.s[i].N = N; pd.s[i].blk0 = off;
        off += (N / 32) * (K / 32);
    };
    seg(0, wk,      wkvT,                    E_, E_);
    seg(1, wv,      wkvT + (size_t)E_ * E_,  E_, E_);
    seg(2, wq,      wqT,                     E_, E_);
    seg(3, wo,      woT,                     E_, E_);
    seg(4, mlpq_w1, mq1T,                    E_, M_);
    seg(5, mlpq_w2, mq2T,                    M_, E_);
    seg(6, mlp_w1,  m1T,                     E_, M_);
    seg(7, mlp_w2,  m2T,                     M_, E_);
    pd.bk = bk; pd.bv = bv; pd.bkvO = bkvC;
    pd.X = inputs; pd.gq = lnq_g; pd.bq = lnq_b; pd.gkv = lnkv_g; pd.bkvLN = lnkv_b;
    pd.out_q = qln; pd.out_kv = kvln;
    const int nblk_t = off;                         // 5120

    DP dp;
    dp.A1 = kvln; dp.B1 = wkvT; dp.bias1 = bkvC; dp.C1 = kv;
    dp.N1 = 1024; dp.K1 = E_; dp.nx1 = 1024 / 128;
    dp.ntiles1 = (ROWS_KV / 128) * dp.nx1;          // 3968
    dp.A2 = qln; dp.B2 = wqT; dp.bias2 = bq; dp.C2 = q;
    dp.N2 = E_; dp.K2 = E_; dp.nx2 = E_ / 128;
    const int ntiles2 = (ROWS_Q / 128) * dp.nx2;    // 16

    // 1) fused pre-work
    pre_all<<<nblk_t + 1 + B_ * HW_ * NF_, 256>>>(pd, nblk_t);
    // 2) kv + q projections in one launch
    hgemm_dual<<<dp.ntiles1 + ntiles2, 128, SMEM_TOTAL>>>(dp);
    // 3) attention -> t1h
    attn_mma<<<B_ * T_ * H_, 256, ATTN_SMEM>>>(q, kv, t1h);
    // 4) out projection: t1h -> t2h
    hgemm<false,false,__half><<<dim3(E_/128, ROWS_KV/128), 128, SMEM_TOTAL>>>(t1h, woT, bo, nullptr, t2h, E_, E_);
    // 5-6) mlp_q: t2h -> hid (GELU) -> t1h (fp16, + residual kvln)
    hgemm<true ,false,__half><<<dim3(M_/128, ROWS_KV/128), 128, SMEM_TOTAL>>>(t2h, mq1T, mlpq_b1, nullptr, hid, M_, E_);
    hgemm<false,true ,__half><<<dim3(E_/128, ROWS_KV/128), 128, SMEM_TOTAL>>>(hid, mq2T, mlpq_b2, kvln,  t1h, E_, M_);
    // 7) res_ln + ln_2 fused: t1h -> t2h
    dual_ln_kernel<<<ROWS_KV, 128>>>(t1h, resln_g, resln_b, ln2_g, ln2_b, t2h);
    // 8-9) final MLP: t2h -> hid (GELU) -> out (fp32)
    hgemm<true ,false,__half><<<dim3(M_/128, ROWS_KV/128), 128, SMEM_TOTAL>>>(t2h, m1T, mlp_b1, nullptr, hid, M_, E_);
    hgemm<false,false,float ><<<dim3(E_/128, ROWS_KV/128), 128, SMEM_TOTAL>>>(hid, m2T, mlp_b2, nullptr, out, E_, M_);
}